// round 3
// baseline (speedup 1.0000x reference)
#include <cuda_runtime.h>
#include <math.h>

// ---------------- problem constants ----------------
constexpr int NB   = 4;      // batch
constexpr int SEQ  = 1024;   // sequence
constexpr int DIN  = 1024;   // in features / model dim
constexpr int NH   = 16;     // heads
constexpr int HD   = 64;     // per-head dim
constexpr int MTOT = NB * SEQ;      // 4096 rows
constexpr size_t OUT1_ELEMS = (size_t)MTOT * DIN;          // 4,194,304
// d_out layout: [ out (4M floats) | attention (64M floats) ]

// ---------------- scratch (device globals; no allocation) ----------------
__device__ float g_QKV[3][(size_t)NB * NH * SEQ * HD];  // per-head Q/K/V [B,H,S,64]
__device__ float g_CTX[OUT1_ELEMS];                     // context [B*S, 1024]
__device__ float g_O1 [OUT1_ELEMS];                     // proj + bias + residual

// =====================================================================
// GEMM: C[m,n] = sum_k X[m,k] * W[k,n]   (M=4096, N=1024, K=1024)
// which 0/1/2 : output scattered to head layout g_QKV[which] (+bias)
// which 3     : output to g_O1 row-major (+bias +residual), X = g_CTX
// Tiles: 64x64 block, 32 K-step, 256 threads, 4x4 per thread.
// =====================================================================
__global__ __launch_bounds__(256) void gemm_kernel(
    const float* __restrict__ X, const float* __restrict__ W,
    const float* __restrict__ bias, const float* __restrict__ resid,
    int which)
{
    __shared__ float As[64][32];
    __shared__ float Bs[32][64];
    const int tid = threadIdx.x;
    const int tx  = tid & 15, ty = tid >> 4;
    const int m0  = blockIdx.y << 6;
    const int n0  = blockIdx.x << 6;
    const float* Xp = (which == 3) ? (const float*)g_CTX : X;

    float acc[4][4] = {};
    for (int k0 = 0; k0 < DIN; k0 += 32) {
        #pragma unroll
        for (int l = 0; l < 2; l++) {             // A: 64x32
            int i = tid + l * 256;
            int r = i >> 3, c = (i & 7) << 2;
            *(float4*)&As[r][c] =
                *(const float4*)(Xp + (size_t)(m0 + r) * DIN + k0 + c);
        }
        #pragma unroll
        for (int l = 0; l < 2; l++) {             // B: 32x64
            int i = tid + l * 256;
            int r = i >> 4, c = (i & 15) << 2;
            *(float4*)&Bs[r][c] =
                *(const float4*)(W + (size_t)(k0 + r) * DIN + n0 + c);
        }
        __syncthreads();
        #pragma unroll 8
        for (int kk = 0; kk < 32; kk++) {
            float a[4];
            #pragma unroll
            for (int i = 0; i < 4; i++) a[i] = As[ty * 4 + i][kk];
            float4 bv = *(float4*)&Bs[kk][tx * 4];
            float b4[4] = {bv.x, bv.y, bv.z, bv.w};
            #pragma unroll
            for (int i = 0; i < 4; i++)
                #pragma unroll
                for (int j = 0; j < 4; j++)
                    acc[i][j] = fmaf(a[i], b4[j], acc[i][j]);
        }
        __syncthreads();
    }

    const int n = n0 + tx * 4;
    float4 bb = *(const float4*)(bias + n);
    if (which < 3) {
        const int h = n0 >> 6;          // n-tile is 64-aligned -> one head per block col
        const int d = tx * 4;
        float* outp = g_QKV[which];
        #pragma unroll
        for (int i = 0; i < 4; i++) {
            int m = m0 + ty * 4 + i;
            int b = m >> 10, s = m & 1023;
            float4 vo = make_float4(acc[i][0] + bb.x, acc[i][1] + bb.y,
                                    acc[i][2] + bb.z, acc[i][3] + bb.w);
            *(float4*)(outp + ((size_t)((b * NH + h) * SEQ + s)) * HD + d) = vo;
        }
    } else {
        #pragma unroll
        for (int i = 0; i < 4; i++) {
            int m = m0 + ty * 4 + i;
            float4 rv = *(const float4*)(resid + (size_t)m * DIN + n);
            float4 vo = make_float4(acc[i][0] + bb.x + rv.x, acc[i][1] + bb.y + rv.y,
                                    acc[i][2] + bb.z + rv.z, acc[i][3] + bb.w + rv.w);
            *(float4*)(g_O1 + (size_t)m * DIN + n) = vo;
        }
    }
}

// =====================================================================
// Flash attention per (b,h, 64-row q tile). Online softmax over 16 k-tiles.
// Writes raw (unscaled, unmasked) logits -> att, context -> g_CTX.
// =====================================================================
constexpr int ATTN_SMEM_FLOATS = 4096 /*Qs*/ + 64 * 65 /*KVs*/ + 4096 /*Ss*/ + 5 * 64;
constexpr int ATTN_SMEM_BYTES  = ATTN_SMEM_FLOATS * 4;   // 50,688

__global__ __launch_bounds__(256) void attn_kernel(
    const float* __restrict__ qmask, const float* __restrict__ kmask,
    float* __restrict__ att)
{
    extern __shared__ float sm[];
    float* Qs   = sm;                    // [64][64]
    float* KVs  = sm + 4096;             // [64][65]  (K tile, later V tile)
    float* Ss   = KVs + 64 * 65;         // [64][64]
    float* rowm = Ss + 4096;             // [64] running max
    float* rowl = rowm + 64;             // [64] running sum
    float* rowa = rowl + 64;             // [64] rescale factor
    float* qmr  = rowa + 64;             // [64] q mask
    float* skm  = qmr + 64;              // [64] k mask (tile)

    const int tid = threadIdx.x;
    const int tx  = tid & 15, ty = tid >> 4;
    const int bh  = blockIdx.y;          // b*16 + h
    const int b   = bh >> 4;
    const int q0  = blockIdx.x << 6;

    const float* QH = g_QKV[0] + (size_t)bh * SEQ * HD;
    const float* KH = g_QKV[1] + (size_t)bh * SEQ * HD;
    const float* VH = g_QKV[2] + (size_t)bh * SEQ * HD;

    #pragma unroll
    for (int l = 0; l < 4; l++) {
        int i = tid + l * 256;
        int r = i >> 4, c = (i & 15) << 2;
        *(float4*)&Qs[r * 64 + c] = *(const float4*)(QH + (size_t)(q0 + r) * HD + c);
    }
    if (tid < 64) {
        qmr[tid]  = qmask[b * SEQ + q0 + tid];
        rowm[tid] = -INFINITY;
        rowl[tid] = 0.f;
    }
    __syncthreads();

    float ctx[4][4] = {};
    const int row = tid >> 2, qq = tid & 3;   // 4 threads per q-row for softmax

    for (int kt = 0; kt < 16; kt++) {
        const int k0 = kt << 6;
        // ---- load K tile (stride-65 to dodge bank conflicts on K^T reads) ----
        #pragma unroll
        for (int l = 0; l < 4; l++) {
            int i = tid + l * 256;
            int r = i >> 4, c = (i & 15) << 2;
            float4 vv = *(const float4*)(KH + (size_t)(k0 + r) * HD + c);
            float* p = &KVs[r * 65 + c];
            p[0] = vv.x; p[1] = vv.y; p[2] = vv.z; p[3] = vv.w;
        }
        if (tid < 64) skm[tid] = kmask[b * SEQ + k0 + tid];
        __syncthreads();

        // ---- S = Q K^T (64x64x64) ----
        float sacc[4][4] = {};
        #pragma unroll 8
        for (int d = 0; d < 64; d++) {
            float a[4], bb[4];
            #pragma unroll
            for (int i = 0; i < 4; i++) a[i]  = Qs[(ty * 4 + i) * 64 + d];
            #pragma unroll
            for (int j = 0; j < 4; j++) bb[j] = KVs[(tx * 4 + j) * 65 + d];
            #pragma unroll
            for (int i = 0; i < 4; i++)
                #pragma unroll
                for (int j = 0; j < 4; j++)
                    sacc[i][j] = fmaf(a[i], bb[j], sacc[i][j]);
        }

        // ---- raw logits: stage to smem + straight to gmem (output #2) ----
        #pragma unroll
        for (int i = 0; i < 4; i++) {
            float4 vo = make_float4(sacc[i][0], sacc[i][1], sacc[i][2], sacc[i][3]);
            *(float4*)&Ss[(ty * 4 + i) * 64 + tx * 4] = vo;
            *(float4*)(att + ((size_t)bh * SEQ + q0 + ty * 4 + i) * SEQ + k0 + tx * 4) = vo;
        }
        __syncthreads();

        // ---- load V tile into same buffer (K reads are done) ----
        #pragma unroll
        for (int l = 0; l < 4; l++) {
            int i = tid + l * 256;
            int r = i >> 4, c = (i & 15) << 2;
            float4 vv = *(const float4*)(VH + (size_t)(k0 + r) * HD + c);
            float* p = &KVs[r * 65 + c];
            p[0] = vv.x; p[1] = vv.y; p[2] = vv.z; p[3] = vv.w;
        }

        // ---- phase 1: tile row-max (masked, scaled) -> update running max ----
        const bool qv = (qmr[row] != 0.f);
        float lm = -INFINITY;
        #pragma unroll
        for (int c = 0; c < 16; c++) {
            int cc = qq * 16 + c;
            float raw = Ss[row * 64 + cc];
            float sv  = (qv && skm[cc] != 0.f) ? raw * 0.125f : -1e9f;
            lm = fmaxf(lm, sv);
        }
        lm = fmaxf(lm, __shfl_xor_sync(0xffffffffu, lm, 1));
        lm = fmaxf(lm, __shfl_xor_sync(0xffffffffu, lm, 2));
        if (qq == 0) {
            float old = rowm[row];
            float nm  = fmaxf(old, lm);
            rowm[row] = nm;
            float al  = __expf(old - nm);   // exp(-inf)=0 on first tile
            rowa[row] = al;
            rowl[row] *= al;
        }
        __syncthreads();

        // ---- phase 2: exponentiate in place + tile row-sum ----
        float nm = rowm[row];
        float ls = 0.f;
        #pragma unroll
        for (int c = 0; c < 16; c++) {
            int cc = qq * 16 + c;
            float raw = Ss[row * 64 + cc];
            float sv  = (qv && skm[cc] != 0.f) ? raw * 0.125f : -1e9f;
            float p   = __expf(sv - nm);    // masked -> exactly 0 (underflow)
            Ss[row * 64 + cc] = p;
            ls += p;
        }
        ls += __shfl_xor_sync(0xffffffffu, ls, 1);
        ls += __shfl_xor_sync(0xffffffffu, ls, 2);
        if (qq == 0) rowl[row] += ls;
        __syncthreads();

        // ---- phase 3: rescale accumulator, ctx += P @ V ----
        #pragma unroll
        for (int i = 0; i < 4; i++) {
            float al = rowa[ty * 4 + i];
            #pragma unroll
            for (int j = 0; j < 4; j++) ctx[i][j] *= al;
        }
        #pragma unroll 8
        for (int kk = 0; kk < 64; kk++) {
            float p[4], vv[4];
            #pragma unroll
            for (int i = 0; i < 4; i++) p[i]  = Ss[(ty * 4 + i) * 64 + kk];
            #pragma unroll
            for (int j = 0; j < 4; j++) vv[j] = KVs[kk * 65 + tx * 4 + j];
            #pragma unroll
            for (int i = 0; i < 4; i++)
                #pragma unroll
                for (int j = 0; j < 4; j++)
                    ctx[i][j] = fmaf(p[i], vv[j], ctx[i][j]);
        }
        __syncthreads();
    }

    // ---- finalize: divide by l; fully-masked q rows -> 0 (matches reference) ----
    const int h = bh & 15;
    #pragma unroll
    for (int i = 0; i < 4; i++) {
        int r = ty * 4 + i;
        float inv = 1.f / rowl[r];
        bool  qv2 = (qmr[r] != 0.f);
        float4 vo;
        vo.x = qv2 ? ctx[i][0] * inv : 0.f;
        vo.y = qv2 ? ctx[i][1] * inv : 0.f;
        vo.z = qv2 ? ctx[i][2] * inv : 0.f;
        vo.w = qv2 ? ctx[i][3] * inv : 0.f;
        *(float4*)(g_CTX + ((size_t)(b * SEQ + q0 + r)) * DIN + h * 64 + tx * 4) = vo;
    }
}

// =====================================================================
// LayerNorm over last dim (1024), one block per row.
// =====================================================================
__global__ __launch_bounds__(256) void ln_kernel(
    const float* __restrict__ gamma, const float* __restrict__ beta,
    float* __restrict__ out)
{
    __shared__ float red[16];
    __shared__ float s_mu, s_rs;
    const int row = blockIdx.x;
    const int tid = threadIdx.x;
    const float* xr = g_O1 + (size_t)row * DIN;
    float4 x = *(const float4*)(xr + tid * 4);
    float s  = x.x + x.y + x.z + x.w;
    float s2 = x.x * x.x + x.y * x.y + x.z * x.z + x.w * x.w;
    #pragma unroll
    for (int o = 16; o; o >>= 1) {
        s  += __shfl_xor_sync(0xffffffffu, s, o);
        s2 += __shfl_xor_sync(0xffffffffu, s2, o);
    }
    if ((tid & 31) == 0) { red[tid >> 5] = s; red[8 + (tid >> 5)] = s2; }
    __syncthreads();
    if (tid == 0) {
        float ts = 0.f, ts2 = 0.f;
        #pragma unroll
        for (int w = 0; w < 8; w++) { ts += red[w]; ts2 += red[8 + w]; }
        float mu  = ts * (1.f / 1024.f);
        float var = ts2 * (1.f / 1024.f) - mu * mu;
        s_mu = mu; s_rs = rsqrtf(var + 1e-5f);
    }
    __syncthreads();
    float mu = s_mu, rs = s_rs;
    float4 g  = *(const float4*)(gamma + tid * 4);
    float4 be = *(const float4*)(beta  + tid * 4);
    float4 o;
    o.x = (x.x - mu) * rs * g.x + be.x;
    o.y = (x.y - mu) * rs * g.y + be.y;
    o.z = (x.z - mu) * rs * g.z + be.z;
    o.w = (x.w - mu) * rs * g.w + be.w;
    *(float4*)(out + (size_t)row * DIN + tid * 4) = o;
}

// =====================================================================
extern "C" void kernel_launch(void* const* d_in, const int* in_sizes, int n_in,
                              void* d_out, int out_size)
{
    const float* q     = (const float*)d_in[0];
    const float* k     = (const float*)d_in[1];
    const float* v     = (const float*)d_in[2];
    const float* qm    = (const float*)d_in[3];
    const float* km    = (const float*)d_in[4];
    const float* Wq    = (const float*)d_in[5];
    const float* bq    = (const float*)d_in[6];
    const float* Wk    = (const float*)d_in[7];
    const float* bk    = (const float*)d_in[8];
    const float* Wv    = (const float*)d_in[9];
    const float* bv    = (const float*)d_in[10];
    const float* Wf    = (const float*)d_in[11];
    const float* bf    = (const float*)d_in[12];
    const float* gamma = (const float*)d_in[13];
    const float* beta  = (const float*)d_in[14];

    float* out = (float*)d_out;
    float* att = out + OUT1_ELEMS;   // second output: raw attention logits

    cudaFuncSetAttribute(attn_kernel, cudaFuncAttributeMaxDynamicSharedMemorySize,
                         ATTN_SMEM_BYTES);

    dim3 gg(DIN / 64, MTOT / 64);    // (16, 64)
    gemm_kernel<<<gg, 256>>>(q, Wq, bq, nullptr, 0);
    gemm_kernel<<<gg, 256>>>(k, Wk, bk, nullptr, 1);
    gemm_kernel<<<gg, 256>>>(v, Wv, bv, nullptr, 2);
    attn_kernel<<<dim3(SEQ / 64, NB * NH), 256, ATTN_SMEM_BYTES>>>(qm, km, att);
    gemm_kernel<<<gg, 256>>>(nullptr, Wf, bf, v, 3);   // X = g_CTX internally
    ln_kernel<<<MTOT, 256>>>(gamma, beta, out);
}

// round 12
// speedup vs baseline: 1.5879x; 1.5879x over previous
#include <cuda_runtime.h>
#include <cuda_bf16.h>
#include <math.h>
#include <stdint.h>

// ---------------- problem constants ----------------
constexpr int NB   = 4;
constexpr int SEQ  = 1024;
constexpr int DIN  = 1024;
constexpr int NH   = 16;
constexpr int MTOT = NB * SEQ;                       // 4096
constexpr size_t OUT1_ELEMS = (size_t)MTOT * DIN;    // 4,194,304
// d_out layout: [ out (4M floats) | attention (64M floats) ]

// ---------------- scratch (device globals; no allocation) ----------------
__device__ float g_QKV[3][OUT1_ELEMS];   // projected q/k/v, [B*S,1024] row-major
__device__ float g_CTX[OUT1_ELEMS];
__device__ float g_O1 [OUT1_ELEMS];
// bf16-split planes (reused across the 4 GEMMs; launches are stream-ordered)
__device__ __nv_bfloat16 g_Xh[OUT1_ELEMS];           // X hi plane [m][k]
__device__ __nv_bfloat16 g_Xl[OUT1_ELEMS];           // X lo plane [m][k]
__device__ __nv_bfloat16 g_Wh[(size_t)DIN * DIN];    // W hi plane TRANSPOSED [n][k]
__device__ __nv_bfloat16 g_Wl[(size_t)DIN * DIN];    // W lo plane TRANSPOSED [n][k]

// =====================================================================
// helpers (plain-sm_103-safe: ldmatrix + mma.sync only, no tcgen05)
// =====================================================================
__device__ __forceinline__ uint32_t smem_u32(const void* p) {
    return (uint32_t)__cvta_generic_to_shared(p);
}

#define LDSM_X4(r, addr)                                                        \
    asm volatile("ldmatrix.sync.aligned.m8n8.x4.shared.b16 {%0,%1,%2,%3}, [%4];"\
        : "=r"((r)[0]), "=r"((r)[1]), "=r"((r)[2]), "=r"((r)[3]) : "r"(addr))

#define MMA_BF16(d, a, b0, b1)                                                  \
    asm volatile("mma.sync.aligned.m16n8k16.row.col.f32.bf16.bf16.f32 "         \
        "{%0,%1,%2,%3}, {%4,%5,%6,%7}, {%8,%9}, {%0,%1,%2,%3};"                 \
        : "+f"((d)[0]), "+f"((d)[1]), "+f"((d)[2]), "+f"((d)[3])                \
        : "r"((a)[0]), "r"((a)[1]), "r"((a)[2]), "r"((a)[3]), "r"(b0), "r"(b1))

// pack two floats to bf16x2 (RN): e0 -> low 16 bits, e1 -> high 16 bits
__device__ __forceinline__ uint32_t pack2(float e0, float e1) {
    uint32_t r;
    asm("cvt.rn.bf16x2.f32 %0, %1, %2;" : "=r"(r) : "f"(e1), "f"(e0));
    return r;
}
__device__ __forceinline__ float lo_half_f(uint32_t p)  { return __uint_as_float(p << 16); }
__device__ __forceinline__ float hi_half_f(uint32_t p)  { return __uint_as_float(p & 0xFFFF0000u); }

__device__ __forceinline__ void split_store4(const float4 v, size_t i) {
    uint32_t hp0 = pack2(v.x, v.y);
    uint32_t hp1 = pack2(v.z, v.w);
    float lx = v.x - lo_half_f(hp0), ly = v.y - hi_half_f(hp0);
    float lz = v.z - lo_half_f(hp1), lw = v.w - hi_half_f(hp1);
    *(uint2*)(g_Xh + i) = make_uint2(hp0, hp1);
    *(uint2*)(g_Xl + i) = make_uint2(pack2(lx, ly), pack2(lz, lw));
}

// =====================================================================
// cvt_x: elementwise fp32 -> (hi, lo) bf16 planes, same [m][k] layout.
// Two variants: from a harness input pointer, and from g_CTX (device symbol),
// so kernel_launch needs no cudaGetSymbolAddress / static caching.
// =====================================================================
__global__ __launch_bounds__(256) void cvt_x(const float* __restrict__ X)
{
    size_t i = ((size_t)blockIdx.x * 256 + threadIdx.x) * 4;
    split_store4(*(const float4*)(X + i), i);
}

__global__ __launch_bounds__(256) void cvt_x_ctx()
{
    size_t i = ((size_t)blockIdx.x * 256 + threadIdx.x) * 4;
    split_store4(*(const float4*)(g_CTX + i), i);
}

// =====================================================================
// cvt_w: W[k][n] fp32 -> transposed bf16 planes g_W{h,l}[n][k].
// 32x32 tiles via smem. grid (32,32) x 256.
// =====================================================================
__global__ __launch_bounds__(256) void cvt_w(const float* __restrict__ W)
{
    __shared__ float t[32][33];
    const int k0 = blockIdx.y * 32, n0 = blockIdx.x * 32;
    const int tx = threadIdx.x & 31, ty = threadIdx.x >> 5;
    #pragma unroll
    for (int p = 0; p < 4; ++p) {
        int r = ty + p * 8;
        t[r][tx] = W[(size_t)(k0 + r) * DIN + n0 + tx];
    }
    __syncthreads();
    const int nl = threadIdx.x >> 4;              // 0..15 n-local
    const int pr = threadIdx.x & 15;              // k-pair
    #pragma unroll
    for (int p = 0; p < 2; ++p) {
        int n = nl + p * 16;
        float a = t[2 * pr][n], b = t[2 * pr + 1][n];
        uint32_t hp = pack2(a, b);
        float la = a - lo_half_f(hp), lb = b - hi_half_f(hp);
        size_t off = (size_t)(n0 + n) * DIN + k0 + 2 * pr;
        *(uint32_t*)(g_Wh + off) = hp;
        *(uint32_t*)(g_Wl + off) = pack2(la, lb);
    }
}

// =====================================================================
// HMMA GEMM: C[m,n] = sum_k X[m,k] W[k,n] via 3 bf16 mma.sync products
// (AhBh + AhBl + AlBh; dropped AlBl term ~2^-16 relative).
// Inputs pre-split: g_Xh/g_Xl [m][k], g_Wh/g_Wl [n][k]  (both K-major).
// CTA tile 128x128, K-chunk 32, 256 threads = 8 warps (4 M x 2 N),
// warp tile 32x64 = 2 m-frags x 8 n-frags of m16n8k16.
// which 0/1/2: out = g_QKV[which] (+bias). which 3: out = g_O1 (+bias+resid).
// =====================================================================
constexpr int SPITCH = 80;                 // bytes per 32-elem bf16 row (16B-aligned, conflict-light)
constexpr int PLANE  = 128 * SPITCH;       // 10240 B
__global__ __launch_bounds__(256) void gemm_mma(
    const float* __restrict__ bias, const float* __restrict__ resid, int which)
{
    __shared__ __align__(16) unsigned char smem[4 * PLANE];   // 40960 B (static)
    const uint32_t sb = smem_u32(smem);

    const int tid = threadIdx.x;
    const int w   = tid >> 5, ln = tid & 31;
    const int wm  = w & 3, wn = w >> 2;            // warp grid 4(M) x 2(N)
    const int m0  = blockIdx.y * 128;
    const int n0  = blockIdx.x * 128;

    const __nv_bfloat16* srcs[4] = {
        g_Xh + (size_t)m0 * DIN, g_Xl + (size_t)m0 * DIN,
        g_Wh + (size_t)n0 * DIN, g_Wl + (size_t)n0 * DIN };

    // per-lane ldmatrix address components
    const int a_r = (ln & 7) + ((ln >> 3) & 1) * 8;   // + wm*32 + mf*16
    const int a_k = ((ln >> 4) & 1) * 8;              // + kk
    const int b_n = (ln & 7) + ((ln >> 4) & 1) * 8;   // + wn*64 + t*16
    const int b_k = ((ln >> 3) & 1) * 8;              // + kk

    float acc[2][8][4];
    #pragma unroll
    for (int i = 0; i < 2; ++i)
        #pragma unroll
        for (int j = 0; j < 8; ++j)
            #pragma unroll
            for (int e = 0; e < 4; ++e) acc[i][j][e] = 0.f;

    for (int ch = 0; ch < 32; ++ch) {
        const int k0 = ch * 32;
        // ---- stage 4 planes: 128 rows x 64B each ----
        #pragma unroll
        for (int pl = 0; pl < 4; ++pl) {
            const __nv_bfloat16* s = srcs[pl] + k0;
            #pragma unroll
            for (int it = 0; it < 2; ++it) {
                int idx = tid + it * 256;         // 0..511 16B-units
                int r = idx >> 2, u = idx & 3;
                uint4 v = *(const uint4*)(s + (size_t)r * DIN + u * 8);
                *(uint4*)(smem + pl * PLANE + r * SPITCH + u * 16) = v;
            }
        }
        __syncthreads();

        #pragma unroll
        for (int kk = 0; kk < 32; kk += 16) {
            uint32_t ah[2][4], al[2][4];
            #pragma unroll
            for (int mf = 0; mf < 2; ++mf) {
                uint32_t aaddr = sb + (wm * 32 + mf * 16 + a_r) * SPITCH + (kk + a_k) * 2;
                LDSM_X4(ah[mf], aaddr);
                LDSM_X4(al[mf], aaddr + PLANE);
            }
            #pragma unroll
            for (int t = 0; t < 4; ++t) {
                uint32_t bh[4], bl[4];
                uint32_t baddr = sb + 2 * PLANE +
                                 (wn * 64 + t * 16 + b_n) * SPITCH + (kk + b_k) * 2;
                LDSM_X4(bh, baddr);
                LDSM_X4(bl, baddr + PLANE);
                #pragma unroll
                for (int mf = 0; mf < 2; ++mf)
                    #pragma unroll
                    for (int hv = 0; hv < 2; ++hv) {
                        float* d = acc[mf][t * 2 + hv];
                        MMA_BF16(d, ah[mf], bh[2 * hv], bh[2 * hv + 1]);   // Ah*Bh
                        MMA_BF16(d, ah[mf], bl[2 * hv], bl[2 * hv + 1]);   // Ah*Bl
                        MMA_BF16(d, al[mf], bh[2 * hv], bh[2 * hv + 1]);   // Al*Bh
                    }
            }
        }
        __syncthreads();
    }

    // ---- epilogue: D frags -> gmem, bias (+resid) ----
    float* outp = (which == 3) ? g_O1 : g_QKV[which];
    const int rbase = m0 + wm * 32 + (ln >> 2);
    const int cbase = n0 + wn * 64 + (ln & 3) * 2;
    #pragma unroll
    for (int mf = 0; mf < 2; ++mf)
        #pragma unroll
        for (int nf = 0; nf < 8; ++nf) {
            int c = cbase + nf * 8;
            float bx = bias[c], by = bias[c + 1];
            #pragma unroll
            for (int half = 0; half < 2; ++half) {
                int r = rbase + mf * 16 + half * 8;
                float ox = acc[mf][nf][2 * half + 0] + bx;
                float oy = acc[mf][nf][2 * half + 1] + by;
                if (which == 3) {
                    float2 rv = *(const float2*)(resid + (size_t)r * DIN + c);
                    ox += rv.x; oy += rv.y;
                }
                *(float2*)(outp + (size_t)r * DIN + c) = make_float2(ox, oy);
            }
        }
}

// =====================================================================
// Flash attention, vectorized-LDS SIMT. Layouts (pad 68):
//   Qt [d][q], KVt = K:[d][k] then V:[k][d], St [k][q]
// All inner-loop smem accesses are 128-bit, broadcast or conflict-free.
// =====================================================================
constexpr int PT = 68;
constexpr int ATT_SMEM = (3 * 64 * PT + 5 * 64) * 4;   // 53504 B

__global__ __launch_bounds__(256) void attn_kernel(
    const float* __restrict__ qmask, const float* __restrict__ kmask,
    float* __restrict__ att)
{
    extern __shared__ float smf[];
    float* Qt   = smf;
    float* KVt  = smf + 64 * PT;
    float* St   = smf + 2 * 64 * PT;
    float* rowm = smf + 3 * 64 * PT;
    float* rowl = rowm + 64;
    float* rowa = rowl + 64;
    float* qmr  = rowa + 64;
    float* skm  = qmr + 64;

    const int tid = threadIdx.x;
    const int tx  = tid & 15, ty = tid >> 4;
    const int bh  = blockIdx.y;
    const int b   = bh >> 4, h = bh & 15;
    const int q0  = blockIdx.x << 6;

    const float* Qb = g_QKV[0] + ((size_t)(b * SEQ + q0)) * DIN + h * 64;
    const float* Kb = g_QKV[1] + ((size_t)(b * SEQ)) * DIN + h * 64;
    const float* Vb = g_QKV[2] + ((size_t)(b * SEQ)) * DIN + h * 64;

    #pragma unroll
    for (int l = 0; l < 4; ++l) {
        int i = tid + l * 256;
        int r = i >> 4, c = (i & 15) << 2;
        float4 v = *(const float4*)(Qb + (size_t)r * DIN + c);
        Qt[(c + 0) * PT + r] = v.x;
        Qt[(c + 1) * PT + r] = v.y;
        Qt[(c + 2) * PT + r] = v.z;
        Qt[(c + 3) * PT + r] = v.w;
    }
    if (tid < 64) {
        qmr[tid]  = qmask[b * SEQ + q0 + tid];
        rowm[tid] = -INFINITY;
        rowl[tid] = 0.f;
    }
    __syncthreads();

    float ctx[4][4] = {};
    const int row = tid >> 2, qq = tid & 3;

    for (int kt = 0; kt < 16; ++kt) {
        const int k0 = kt << 6;

        #pragma unroll
        for (int l = 0; l < 4; ++l) {
            int i = tid + l * 256;
            int r = i >> 4, c = (i & 15) << 2;
            float4 v = *(const float4*)(Kb + (size_t)(k0 + r) * DIN + c);
            KVt[(c + 0) * PT + r] = v.x;
            KVt[(c + 1) * PT + r] = v.y;
            KVt[(c + 2) * PT + r] = v.z;
            KVt[(c + 3) * PT + r] = v.w;
        }
        if (tid < 64) skm[tid] = kmask[b * SEQ + k0 + tid];
        __syncthreads();

        float sacc[4][4] = {};
        #pragma unroll 8
        for (int d = 0; d < 64; ++d) {
            float4 a4 = *(const float4*)(Qt  + d * PT + ty * 4);
            float4 b4 = *(const float4*)(KVt + d * PT + tx * 4);
            float a[4] = {a4.x, a4.y, a4.z, a4.w};
            float bb[4] = {b4.x, b4.y, b4.z, b4.w};
            #pragma unroll
            for (int i = 0; i < 4; ++i)
                #pragma unroll
                for (int j = 0; j < 4; ++j)
                    sacc[i][j] = fmaf(a[i], bb[j], sacc[i][j]);
        }

        #pragma unroll
        for (int i = 0; i < 4; ++i) {
            float4 vo = make_float4(sacc[i][0], sacc[i][1], sacc[i][2], sacc[i][3]);
            *(float4*)(att + ((size_t)bh * SEQ + q0 + ty * 4 + i) * SEQ + k0 + tx * 4) = vo;
            #pragma unroll
            for (int j = 0; j < 4; ++j)
                St[(tx * 4 + j) * PT + ty * 4 + i] = sacc[i][j];
        }
        __syncthreads();

        #pragma unroll
        for (int l = 0; l < 4; ++l) {
            int i = tid + l * 256;
            int r = i >> 4, c = (i & 15) << 2;
            *(float4*)(KVt + r * PT + c) =
                *(const float4*)(Vb + (size_t)(k0 + r) * DIN + c);
        }

        const bool qv = (qmr[row] != 0.f);
        float lm = -INFINITY;
        #pragma unroll
        for (int c = 0; c < 16; ++c) {
            int cc = qq * 16 + c;
            float raw = St[cc * PT + row];
            float sv  = (qv && skm[cc] != 0.f) ? raw * 0.125f : -1e9f;
            lm = fmaxf(lm, sv);
        }
        lm = fmaxf(lm, __shfl_xor_sync(0xffffffffu, lm, 1));
        lm = fmaxf(lm, __shfl_xor_sync(0xffffffffu, lm, 2));
        if (qq == 0) {
            float old = rowm[row];
            float nm  = fmaxf(old, lm);
            rowm[row] = nm;
            float al  = __expf(old - nm);
            rowa[row] = al;
            rowl[row] *= al;
        }
        __syncthreads();

        float nm = rowm[row];
        float ls = 0.f;
        #pragma unroll
        for (int c = 0; c < 16; ++c) {
            int cc = qq * 16 + c;
            float raw = St[cc * PT + row];
            float sv  = (qv && skm[cc] != 0.f) ? raw * 0.125f : -1e9f;
            float p   = __expf(sv - nm);
            St[cc * PT + row] = p;
            ls += p;
        }
        ls += __shfl_xor_sync(0xffffffffu, ls, 1);
        ls += __shfl_xor_sync(0xffffffffu, ls, 2);
        if (qq == 0) rowl[row] += ls;
        __syncthreads();

        #pragma unroll
        for (int i = 0; i < 4; ++i) {
            float al = rowa[ty * 4 + i];
            #pragma unroll
            for (int j = 0; j < 4; ++j) ctx[i][j] *= al;
        }
        #pragma unroll 8
        for (int kk = 0; kk < 64; ++kk) {
            float4 p4 = *(const float4*)(St  + kk * PT + ty * 4);
            float4 v4 = *(const float4*)(KVt + kk * PT + tx * 4);
            float p[4] = {p4.x, p4.y, p4.z, p4.w};
            float vv[4] = {v4.x, v4.y, v4.z, v4.w};
            #pragma unroll
            for (int i = 0; i < 4; ++i)
                #pragma unroll
                for (int j = 0; j < 4; ++j)
                    ctx[i][j] = fmaf(p[i], vv[j], ctx[i][j]);
        }
        __syncthreads();
    }

    #pragma unroll
    for (int i = 0; i < 4; ++i) {
        int r = ty * 4 + i;
        float inv = 1.f / rowl[r];
        bool  qv2 = (qmr[r] != 0.f);
        float4 vo;
        vo.x = qv2 ? ctx[i][0] * inv : 0.f;
        vo.y = qv2 ? ctx[i][1] * inv : 0.f;
        vo.z = qv2 ? ctx[i][2] * inv : 0.f;
        vo.w = qv2 ? ctx[i][3] * inv : 0.f;
        *(float4*)(g_CTX + ((size_t)(b * SEQ + q0 + r)) * DIN + h * 64 + tx * 4) = vo;
    }
}

// =====================================================================
// LayerNorm over last dim (1024), one block per row.
// =====================================================================
__global__ __launch_bounds__(256) void ln_kernel(
    const float* __restrict__ gamma, const float* __restrict__ beta,
    float* __restrict__ out)
{
    __shared__ float red[16];
    __shared__ float s_mu, s_rs;
    const int row = blockIdx.x;
    const int tid = threadIdx.x;
    const float* xr = g_O1 + (size_t)row * DIN;
    float4 x = *(const float4*)(xr + tid * 4);
    float s  = x.x + x.y + x.z + x.w;
    float s2 = x.x * x.x + x.y * x.y + x.z * x.z + x.w * x.w;
    #pragma unroll
    for (int o = 16; o; o >>= 1) {
        s  += __shfl_xor_sync(0xffffffffu, s, o);
        s2 += __shfl_xor_sync(0xffffffffu, s2, o);
    }
    if ((tid & 31) == 0) { red[tid >> 5] = s; red[8 + (tid >> 5)] = s2; }
    __syncthreads();
    if (tid == 0) {
        float ts = 0.f, ts2 = 0.f;
        #pragma unroll
        for (int w = 0; w < 8; w++) { ts += red[w]; ts2 += red[8 + w]; }
        float mu  = ts * (1.f / 1024.f);
        float var = ts2 * (1.f / 1024.f) - mu * mu;
        s_mu = mu; s_rs = rsqrtf(var + 1e-5f);
    }
    __syncthreads();
    float mu = s_mu, rs = s_rs;
    float4 g  = *(const float4*)(gamma + tid * 4);
    float4 be = *(const float4*)(beta  + tid * 4);
    float4 o;
    o.x = (x.x - mu) * rs * g.x + be.x;
    o.y = (x.y - mu) * rs * g.y + be.y;
    o.z = (x.z - mu) * rs * g.z + be.z;
    o.w = (x.w - mu) * rs * g.w + be.w;
    *(float4*)(out + (size_t)row * DIN + tid * 4) = o;
}

// =====================================================================
extern "C" void kernel_launch(void* const* d_in, const int* in_sizes, int n_in,
                              void* d_out, int out_size)
{
    const float* q     = (const float*)d_in[0];
    const float* k     = (const float*)d_in[1];
    const float* v     = (const float*)d_in[2];
    const float* qm    = (const float*)d_in[3];
    const float* km    = (const float*)d_in[4];
    const float* Wq    = (const float*)d_in[5];
    const float* bq    = (const float*)d_in[6];
    const float* Wk    = (const float*)d_in[7];
    const float* bk    = (const float*)d_in[8];
    const float* Wv    = (const float*)d_in[9];
    const float* bv    = (const float*)d_in[10];
    const float* Wf    = (const float*)d_in[11];
    const float* bf    = (const float*)d_in[12];
    const float* gamma = (const float*)d_in[13];
    const float* beta  = (const float*)d_in[14];

    float* out = (float*)d_out;
    float* att = out + OUT1_ELEMS;

    cudaFuncSetAttribute(attn_kernel, cudaFuncAttributeMaxDynamicSharedMemorySize, ATT_SMEM);

    const int cvx_blocks = (int)(OUT1_ELEMS / (4 * 256));   // 4096
    const dim3 cw(32, 32);
    const dim3 gg(DIN / 128, MTOT / 128);                   // (8, 32)

    cvt_x<<<cvx_blocks, 256>>>(q);
    cvt_w<<<cw, 256>>>(Wq);
    gemm_mma<<<gg, 256>>>(bq, nullptr, 0);

    cvt_x<<<cvx_blocks, 256>>>(k);
    cvt_w<<<cw, 256>>>(Wk);
    gemm_mma<<<gg, 256>>>(bk, nullptr, 1);

    cvt_x<<<cvx_blocks, 256>>>(v);
    cvt_w<<<cw, 256>>>(Wv);
    gemm_mma<<<gg, 256>>>(bv, nullptr, 2);

    attn_kernel<<<dim3(SEQ / 64, NB * NH), 256, ATT_SMEM>>>(qm, km, att);

    cvt_x_ctx<<<cvx_blocks, 256>>>();
    cvt_w<<<cw, 256>>>(Wf);
    gemm_mma<<<gg, 256>>>(bf, v, 3);

    ln_kernel<<<MTOT, 256>>>(gamma, beta, out);
}

// round 13
// speedup vs baseline: 2.5394x; 1.5992x over previous
#include <cuda_runtime.h>
#include <cuda_bf16.h>
#include <math.h>
#include <stdint.h>

// ---------------- problem constants ----------------
constexpr int NB   = 4;
constexpr int SEQ  = 1024;
constexpr int DIN  = 1024;
constexpr int NH   = 16;
constexpr int MTOT = NB * SEQ;                       // 4096
constexpr size_t OUT1_ELEMS = (size_t)MTOT * DIN;    // 4,194,304
// d_out layout: [ out (4M floats) | attention (64M floats) ]

// ---------------- scratch (device globals; no allocation) ----------------
__device__ float g_O1 [OUT1_ELEMS];                  // final proj + bias + resid
// bf16-split planes for GEMM inputs (X reused across GEMMs)
__device__ __nv_bfloat16 g_Xh[OUT1_ELEMS];           // X hi plane [m][k]
__device__ __nv_bfloat16 g_Xl[OUT1_ELEMS];           // X lo plane [m][k]
__device__ __nv_bfloat16 g_Wh[(size_t)DIN * DIN];    // W hi plane TRANSPOSED [n][k]
__device__ __nv_bfloat16 g_Wl[(size_t)DIN * DIN];    // W lo plane TRANSPOSED [n][k]
// projected Q/K/V in bf16-split head layout [(b*NH+h)*SEQ + s][64]
__device__ __nv_bfloat16 g_sH[3][OUT1_ELEMS];
__device__ __nv_bfloat16 g_sL[3][OUT1_ELEMS];

// =====================================================================
// helpers (plain-sm_103-safe: ldmatrix + mma.sync only)
// =====================================================================
__device__ __forceinline__ uint32_t smem_u32(const void* p) {
    return (uint32_t)__cvta_generic_to_shared(p);
}

#define LDSM_X4(r, addr)                                                        \
    asm volatile("ldmatrix.sync.aligned.m8n8.x4.shared.b16 {%0,%1,%2,%3}, [%4];"\
        : "=r"((r)[0]), "=r"((r)[1]), "=r"((r)[2]), "=r"((r)[3]) : "r"(addr))

#define LDSM_X4_T(r, addr)                                                      \
    asm volatile("ldmatrix.sync.aligned.m8n8.x4.trans.shared.b16 {%0,%1,%2,%3}, [%4];"\
        : "=r"((r)[0]), "=r"((r)[1]), "=r"((r)[2]), "=r"((r)[3]) : "r"(addr))

#define MMA_BF16(d, a, b0, b1)                                                  \
    asm volatile("mma.sync.aligned.m16n8k16.row.col.f32.bf16.bf16.f32 "         \
        "{%0,%1,%2,%3}, {%4,%5,%6,%7}, {%8,%9}, {%0,%1,%2,%3};"                 \
        : "+f"((d)[0]), "+f"((d)[1]), "+f"((d)[2]), "+f"((d)[3])                \
        : "r"((a)[0]), "r"((a)[1]), "r"((a)[2]), "r"((a)[3]), "r"(b0), "r"(b1))

// pack two floats to bf16x2 (RN): e0 -> low 16 bits, e1 -> high 16 bits
__device__ __forceinline__ uint32_t pack2(float e0, float e1) {
    uint32_t r;
    asm("cvt.rn.bf16x2.f32 %0, %1, %2;" : "=r"(r) : "f"(e1), "f"(e0));
    return r;
}
__device__ __forceinline__ float lo_half_f(uint32_t p)  { return __uint_as_float(p << 16); }
__device__ __forceinline__ float hi_half_f(uint32_t p)  { return __uint_as_float(p & 0xFFFF0000u); }

// =====================================================================
// cvt_x: elementwise fp32 -> (hi, lo) bf16 planes, same [m][k] layout.
// =====================================================================
__global__ __launch_bounds__(256) void cvt_x(const float* __restrict__ X)
{
    size_t i = ((size_t)blockIdx.x * 256 + threadIdx.x) * 4;
    float4 v = *(const float4*)(X + i);
    uint32_t hp0 = pack2(v.x, v.y);
    uint32_t hp1 = pack2(v.z, v.w);
    float lx = v.x - lo_half_f(hp0), ly = v.y - hi_half_f(hp0);
    float lz = v.z - lo_half_f(hp1), lw = v.w - hi_half_f(hp1);
    *(uint2*)(g_Xh + i) = make_uint2(hp0, hp1);
    *(uint2*)(g_Xl + i) = make_uint2(pack2(lx, ly), pack2(lz, lw));
}

// =====================================================================
// cvt_w: W[k][n] fp32 -> transposed bf16 planes g_W{h,l}[n][k].
// =====================================================================
__global__ __launch_bounds__(256) void cvt_w(const float* __restrict__ W)
{
    __shared__ float t[32][33];
    const int k0 = blockIdx.y * 32, n0 = blockIdx.x * 32;
    const int tx = threadIdx.x & 31, ty = threadIdx.x >> 5;
    #pragma unroll
    for (int p = 0; p < 4; ++p) {
        int r = ty + p * 8;
        t[r][tx] = W[(size_t)(k0 + r) * DIN + n0 + tx];
    }
    __syncthreads();
    const int nl = threadIdx.x >> 4;
    const int pr = threadIdx.x & 15;
    #pragma unroll
    for (int p = 0; p < 2; ++p) {
        int n = nl + p * 16;
        float a = t[2 * pr][n], b = t[2 * pr + 1][n];
        uint32_t hp = pack2(a, b);
        float la = a - lo_half_f(hp), lb = b - hi_half_f(hp);
        size_t off = (size_t)(n0 + n) * DIN + k0 + 2 * pr;
        *(uint32_t*)(g_Wh + off) = hp;
        *(uint32_t*)(g_Wl + off) = pack2(la, lb);
    }
}

// =====================================================================
// HMMA GEMM (validated R12): C = X W via 3 bf16 products.
// which 0/1/2: epilogue -> bf16 hi/lo head-layout planes g_sH/g_sL[which].
// which 3    : epilogue -> g_O1 fp32 (+bias +resid).
// =====================================================================
constexpr int SPITCH = 80;
constexpr int PLANE  = 128 * SPITCH;       // 10240 B
__global__ __launch_bounds__(256) void gemm_mma(
    const float* __restrict__ bias, const float* __restrict__ resid, int which)
{
    __shared__ __align__(16) unsigned char smem[4 * PLANE];   // 40960 B
    const uint32_t sb = smem_u32(smem);

    const int tid = threadIdx.x;
    const int w   = tid >> 5, ln = tid & 31;
    const int wm  = w & 3, wn = w >> 2;
    const int m0  = blockIdx.y * 128;
    const int n0  = blockIdx.x * 128;

    const __nv_bfloat16* srcs[4] = {
        g_Xh + (size_t)m0 * DIN, g_Xl + (size_t)m0 * DIN,
        g_Wh + (size_t)n0 * DIN, g_Wl + (size_t)n0 * DIN };

    const int a_r = (ln & 7) + ((ln >> 3) & 1) * 8;
    const int a_k = ((ln >> 4) & 1) * 8;
    const int b_n = (ln & 7) + ((ln >> 4) & 1) * 8;
    const int b_k = ((ln >> 3) & 1) * 8;

    float acc[2][8][4];
    #pragma unroll
    for (int i = 0; i < 2; ++i)
        #pragma unroll
        for (int j = 0; j < 8; ++j)
            #pragma unroll
            for (int e = 0; e < 4; ++e) acc[i][j][e] = 0.f;

    for (int ch = 0; ch < 32; ++ch) {
        const int k0 = ch * 32;
        #pragma unroll
        for (int pl = 0; pl < 4; ++pl) {
            const __nv_bfloat16* s = srcs[pl] + k0;
            #pragma unroll
            for (int it = 0; it < 2; ++it) {
                int idx = tid + it * 256;
                int r = idx >> 2, u = idx & 3;
                uint4 v = *(const uint4*)(s + (size_t)r * DIN + u * 8);
                *(uint4*)(smem + pl * PLANE + r * SPITCH + u * 16) = v;
            }
        }
        __syncthreads();

        #pragma unroll
        for (int kk = 0; kk < 32; kk += 16) {
            uint32_t ah[2][4], al[2][4];
            #pragma unroll
            for (int mf = 0; mf < 2; ++mf) {
                uint32_t aaddr = sb + (wm * 32 + mf * 16 + a_r) * SPITCH + (kk + a_k) * 2;
                LDSM_X4(ah[mf], aaddr);
                LDSM_X4(al[mf], aaddr + PLANE);
            }
            #pragma unroll
            for (int t = 0; t < 4; ++t) {
                uint32_t bh[4], bl[4];
                uint32_t baddr = sb + 2 * PLANE +
                                 (wn * 64 + t * 16 + b_n) * SPITCH + (kk + b_k) * 2;
                LDSM_X4(bh, baddr);
                LDSM_X4(bl, baddr + PLANE);
                #pragma unroll
                for (int mf = 0; mf < 2; ++mf)
                    #pragma unroll
                    for (int hv = 0; hv < 2; ++hv) {
                        float* d = acc[mf][t * 2 + hv];
                        MMA_BF16(d, ah[mf], bh[2 * hv], bh[2 * hv + 1]);
                        MMA_BF16(d, ah[mf], bl[2 * hv], bl[2 * hv + 1]);
                        MMA_BF16(d, al[mf], bh[2 * hv], bh[2 * hv + 1]);
                    }
            }
        }
        __syncthreads();
    }

    const int rbase = m0 + wm * 32 + (ln >> 2);
    const int cbase = n0 + wn * 64 + (ln & 3) * 2;
    if (which < 3) {
        // bf16-split head-layout epilogue: row m -> (b, s); col c -> (h, d)
        __nv_bfloat16* oh = g_sH[which];
        __nv_bfloat16* ol = g_sL[which];
        #pragma unroll
        for (int mf = 0; mf < 2; ++mf)
            #pragma unroll
            for (int nf = 0; nf < 8; ++nf) {
                int c = cbase + nf * 8;
                int h = c >> 6, d = c & 63;
                float bx = bias[c], by = bias[c + 1];
                #pragma unroll
                for (int half = 0; half < 2; ++half) {
                    int m = rbase + mf * 16 + half * 8;
                    int b = m >> 10, s = m & 1023;
                    float ox = acc[mf][nf][2 * half + 0] + bx;
                    float oy = acc[mf][nf][2 * half + 1] + by;
                    uint32_t hp = pack2(ox, oy);
                    uint32_t lp = pack2(ox - lo_half_f(hp), oy - hi_half_f(hp));
                    size_t off = ((size_t)((b * NH + h) * SEQ + s)) * 64 + d;
                    *(uint32_t*)(oh + off) = hp;
                    *(uint32_t*)(ol + off) = lp;
                }
            }
    } else {
        #pragma unroll
        for (int mf = 0; mf < 2; ++mf)
            #pragma unroll
            for (int nf = 0; nf < 8; ++nf) {
                int c = cbase + nf * 8;
                float bx = bias[c], by = bias[c + 1];
                #pragma unroll
                for (int half = 0; half < 2; ++half) {
                    int r = rbase + mf * 16 + half * 8;
                    float2 rv = *(const float2*)(resid + (size_t)r * DIN + c);
                    float ox = acc[mf][nf][2 * half + 0] + bx + rv.x;
                    float oy = acc[mf][nf][2 * half + 1] + by + rv.y;
                    *(float2*)(g_O1 + (size_t)r * DIN + c) = make_float2(ox, oy);
                }
            }
    }
}

// =====================================================================
// Tensor-core flash attention.
// Block: (b,h) x 64-row q-tile. 8 warps: wm = q-band (16 rows), wn = kseq half (32).
// QK^T and P V via mma.sync bf16 split-3. In-register softmax, cross-warp
// combine via smem. Raw logits -> att. Finalize -> bf16 split planes g_Xh/g_Xl.
// =====================================================================
constexpr int APB = 144;     // bytes per 64-elem bf16 row (72 elems, conflict-free ldsm)
constexpr int APLANE = 64 * APB;              // 9216
constexpr int OFF_QH = 0;
constexpr int OFF_QL = OFF_QH + APLANE;       // 9216
constexpr int OFF_KH = OFF_QL + APLANE;       // 18432 (reused for Vh)
constexpr int OFF_KL = OFF_KH + APLANE;       // 27648 (reused for Vl)
constexpr int OFF_PM = OFF_KL + APLANE;       // 36864: pm[64][2] f32
constexpr int OFF_PS = OFF_PM + 512;          // 37376: ps[64][2] f32
constexpr int OFF_RM = OFF_PS + 512;          // 37888: rowM[64]
constexpr int OFF_RL = OFF_RM + 256;          // 38144: rowL[64]
constexpr int OFF_QM = OFF_RL + 256;          // 38400: qmr[64]
constexpr int OFF_KM = OFF_QM + 256;          // 38656: skm[64]
constexpr int ATT_SM = OFF_KM + 256;          // 38912 B (static, < 48KB)
// finalize combine buffer aliases Qh/Ql region: [64][66] f32 = 16896 B

__global__ __launch_bounds__(256) void attn_mma(
    const float* __restrict__ qmask, const float* __restrict__ kmask,
    float* __restrict__ att)
{
    __shared__ __align__(16) unsigned char SM[ATT_SM];
    const uint32_t sb = smem_u32(SM);
    float* pm   = (float*)(SM + OFF_PM);
    float* ps   = (float*)(SM + OFF_PS);
    float* rowM = (float*)(SM + OFF_RM);
    float* rowL = (float*)(SM + OFF_RL);
    float* qmr  = (float*)(SM + OFF_QM);
    float* skm  = (float*)(SM + OFF_KM);

    const int tid = threadIdx.x;
    const int w   = tid >> 5, ln = tid & 31;
    const int wm  = w & 3, wn = w >> 2;
    const int g   = ln >> 2, t = ln & 3;
    const int bh  = blockIdx.y;
    const int b   = bh >> 4, h = bh & 15;
    const int q0  = blockIdx.x << 6;

    // ldmatrix lane-address components (identical conventions to gemm_mma)
    const int a_r = (ln & 7) + ((ln >> 3) & 1) * 8;
    const int a_k = ((ln >> 4) & 1) * 8;
    const int b_n = (ln & 7) + ((ln >> 4) & 1) * 8;
    const int b_k = ((ln >> 3) & 1) * 8;
    const int v_r = (ln & 7) + ((ln >> 3) & 1) * 8;   // kseq row within 16
    const int v_c = ((ln >> 4) & 1) * 8;              // d col within 16

    // ---- load Q planes (bf16, already split by gemm epilogue) ----
    {
        const __nv_bfloat16* qh = g_sH[0] + ((size_t)bh * SEQ + q0) * 64;
        const __nv_bfloat16* ql = g_sL[0] + ((size_t)bh * SEQ + q0) * 64;
        #pragma unroll
        for (int it = 0; it < 2; ++it) {
            int idx = tid + it * 256;             // 0..511 16B units
            int r = idx >> 3, u = idx & 7;
            *(uint4*)(SM + OFF_QH + r * APB + u * 16) = *(const uint4*)(qh + r * 64 + u * 8);
            *(uint4*)(SM + OFF_QL + r * APB + u * 16) = *(const uint4*)(ql + r * 64 + u * 8);
        }
    }
    if (tid < 64) {
        qmr[tid]  = qmask[b * SEQ + q0 + tid];
        rowM[tid] = -INFINITY;
        rowL[tid] = 0.f;
    }

    float cacc[8][4];
    #pragma unroll
    for (int i = 0; i < 8; ++i)
        #pragma unroll
        for (int e = 0; e < 4; ++e) cacc[i][e] = 0.f;

    const int r0 = wm * 16 + g;       // this lane's first q row (local)
    const int r1 = r0 + 8;

    for (int kt = 0; kt < 16; ++kt) {
        const int k0 = kt << 6;
        __syncthreads();   // prev tile's V reads done; K/V buffer reusable

        // ---- stage K tile planes ----
        {
            const __nv_bfloat16* kh = g_sH[1] + ((size_t)bh * SEQ + k0) * 64;
            const __nv_bfloat16* kl = g_sL[1] + ((size_t)bh * SEQ + k0) * 64;
            #pragma unroll
            for (int it = 0; it < 2; ++it) {
                int idx = tid + it * 256;
                int r = idx >> 3, u = idx & 7;
                *(uint4*)(SM + OFF_KH + r * APB + u * 16) = *(const uint4*)(kh + r * 64 + u * 8);
                *(uint4*)(SM + OFF_KL + r * APB + u * 16) = *(const uint4*)(kl + r * 64 + u * 8);
            }
        }
        if (tid < 64) skm[tid] = kmask[b * SEQ + k0 + tid];
        __syncthreads();

        // ---- S = Q K^T (split-3): warp covers rows wm*16..+15, cols wn*32..+31 ----
        float sacc[4][4];
        #pragma unroll
        for (int i = 0; i < 4; ++i)
            #pragma unroll
            for (int e = 0; e < 4; ++e) sacc[i][e] = 0.f;
        #pragma unroll
        for (int kc = 0; kc < 4; ++kc) {
            uint32_t qh4[4], ql4[4];
            uint32_t aaddr = sb + OFF_QH + (wm * 16 + a_r) * APB + (kc * 16 + a_k) * 2;
            LDSM_X4(qh4, aaddr);
            LDSM_X4(ql4, aaddr + APLANE);
            #pragma unroll
            for (int tt = 0; tt < 2; ++tt) {
                uint32_t kh4[4], kl4[4];
                uint32_t baddr = sb + OFF_KH + (wn * 32 + tt * 16 + b_n) * APB + (kc * 16 + b_k) * 2;
                LDSM_X4(kh4, baddr);
                LDSM_X4(kl4, baddr + APLANE);
                #pragma unroll
                for (int hv = 0; hv < 2; ++hv) {
                    float* d = sacc[tt * 2 + hv];
                    MMA_BF16(d, qh4, kh4[2 * hv], kh4[2 * hv + 1]);
                    MMA_BF16(d, qh4, kl4[2 * hv], kl4[2 * hv + 1]);
                    MMA_BF16(d, ql4, kh4[2 * hv], kh4[2 * hv + 1]);
                }
            }
        }

        // ---- raw logits -> gmem (output #2) ----
        {
            size_t ar = (size_t)bh * SEQ + q0 + r0;
            #pragma unroll
            for (int nf = 0; nf < 4; ++nf) {
                size_t cb = (size_t)k0 + wn * 32 + nf * 8 + t * 2;
                *(float2*)(att + ar * SEQ + cb)       = make_float2(sacc[nf][0], sacc[nf][1]);
                *(float2*)(att + (ar + 8) * SEQ + cb) = make_float2(sacc[nf][2], sacc[nf][3]);
            }
        }

        // ---- mask + scale ----
        const bool qv0 = (qmr[r0] != 0.f), qv1 = (qmr[r1] != 0.f);
        float sv[4][4];
        #pragma unroll
        for (int nf = 0; nf < 4; ++nf) {
            int col = wn * 32 + nf * 8 + t * 2;
            bool k0m = (skm[col] != 0.f), k1m = (skm[col + 1] != 0.f);
            sv[nf][0] = (qv0 && k0m) ? sacc[nf][0] * 0.125f : -1e9f;
            sv[nf][1] = (qv0 && k1m) ? sacc[nf][1] * 0.125f : -1e9f;
            sv[nf][2] = (qv1 && k0m) ? sacc[nf][2] * 0.125f : -1e9f;
            sv[nf][3] = (qv1 && k1m) ? sacc[nf][3] * 0.125f : -1e9f;
        }

        // ---- phase A: row max (warp-local 32 cols -> smem partials) ----
        float m0 = -INFINITY, m1 = -INFINITY;
        #pragma unroll
        for (int nf = 0; nf < 4; ++nf) {
            m0 = fmaxf(m0, fmaxf(sv[nf][0], sv[nf][1]));
            m1 = fmaxf(m1, fmaxf(sv[nf][2], sv[nf][3]));
        }
        m0 = fmaxf(m0, __shfl_xor_sync(0xffffffffu, m0, 1));
        m0 = fmaxf(m0, __shfl_xor_sync(0xffffffffu, m0, 2));
        m1 = fmaxf(m1, __shfl_xor_sync(0xffffffffu, m1, 1));
        m1 = fmaxf(m1, __shfl_xor_sync(0xffffffffu, m1, 2));
        if (t == 0) { pm[r0 * 2 + wn] = m0; pm[r1 * 2 + wn] = m1; }
        __syncthreads();          // partials visible; all K ldmatrix reads done

        // ---- stage V tile (reuses K buffers) while reading partials ----
        {
            const __nv_bfloat16* vh = g_sH[2] + ((size_t)bh * SEQ + k0) * 64;
            const __nv_bfloat16* vl = g_sL[2] + ((size_t)bh * SEQ + k0) * 64;
            #pragma unroll
            for (int it = 0; it < 2; ++it) {
                int idx = tid + it * 256;
                int r = idx >> 3, u = idx & 7;
                *(uint4*)(SM + OFF_KH + r * APB + u * 16) = *(const uint4*)(vh + r * 64 + u * 8);
                *(uint4*)(SM + OFF_KL + r * APB + u * 16) = *(const uint4*)(vl + r * 64 + u * 8);
            }
        }
        float mo0 = rowM[r0], mo1 = rowM[r1];
        float mn0 = fmaxf(mo0, fmaxf(pm[r0 * 2], pm[r0 * 2 + 1]));
        float mn1 = fmaxf(mo1, fmaxf(pm[r1 * 2], pm[r1 * 2 + 1]));
        float al0 = __expf(mo0 - mn0);
        float al1 = __expf(mo1 - mn1);
        __syncthreads();          // V staged; everyone read old rowM/pm
        if (wn == 0 && t == 0) { rowM[r0] = mn0; rowM[r1] = mn1; }

        // ---- phase B: exponentiate + row sums ----
        float pf[4][4];
        float ls0 = 0.f, ls1 = 0.f;
        #pragma unroll
        for (int nf = 0; nf < 4; ++nf) {
            pf[nf][0] = __expf(sv[nf][0] - mn0);
            pf[nf][1] = __expf(sv[nf][1] - mn0);
            pf[nf][2] = __expf(sv[nf][2] - mn1);
            pf[nf][3] = __expf(sv[nf][3] - mn1);
            ls0 += pf[nf][0] + pf[nf][1];
            ls1 += pf[nf][2] + pf[nf][3];
        }
        ls0 += __shfl_xor_sync(0xffffffffu, ls0, 1);
        ls0 += __shfl_xor_sync(0xffffffffu, ls0, 2);
        ls1 += __shfl_xor_sync(0xffffffffu, ls1, 1);
        ls1 += __shfl_xor_sync(0xffffffffu, ls1, 2);
        if (t == 0) { ps[r0 * 2 + wn] = ls0; ps[r1 * 2 + wn] = ls1; }
        __syncthreads();
        if (wn == 0 && t == 0) {
            rowL[r0] = rowL[r0] * al0 + ps[r0 * 2] + ps[r0 * 2 + 1];
            rowL[r1] = rowL[r1] * al1 + ps[r1 * 2] + ps[r1 * 2 + 1];
        }

        // ---- rescale ctx ----
        #pragma unroll
        for (int i = 0; i < 8; ++i) {
            cacc[i][0] *= al0; cacc[i][1] *= al0;
            cacc[i][2] *= al1; cacc[i][3] *= al1;
        }

        // ---- P fragments (S-accum layout == A-frag layout) ----
        uint32_t pAh[2][4], pAl[2][4];
        #pragma unroll
        for (int kb = 0; kb < 2; ++kb) {
            float e00 = pf[2 * kb][0],     e01 = pf[2 * kb][1];
            float e10 = pf[2 * kb][2],     e11 = pf[2 * kb][3];
            float f00 = pf[2 * kb + 1][0], f01 = pf[2 * kb + 1][1];
            float f10 = pf[2 * kb + 1][2], f11 = pf[2 * kb + 1][3];
            uint32_t h0 = pack2(e00, e01), h1 = pack2(e10, e11);
            uint32_t h2 = pack2(f00, f01), h3 = pack2(f10, f11);
            pAh[kb][0] = h0; pAh[kb][1] = h1; pAh[kb][2] = h2; pAh[kb][3] = h3;
            pAl[kb][0] = pack2(e00 - lo_half_f(h0), e01 - hi_half_f(h0));
            pAl[kb][1] = pack2(e10 - lo_half_f(h1), e11 - hi_half_f(h1));
            pAl[kb][2] = pack2(f00 - lo_half_f(h2), f01 - hi_half_f(h2));
            pAl[kb][3] = pack2(f10 - lo_half_f(h3), f11 - hi_half_f(h3));
        }

        // ---- ctx += P V (warp's kseq half; V^T via ldmatrix.trans) ----
        #pragma unroll
        for (int kb = 0; kb < 2; ++kb) {
            const int kbase = wn * 32 + kb * 16;
            #pragma unroll
            for (int dt = 0; dt < 4; ++dt) {
                uint32_t vh4[4], vl4[4];
                uint32_t vaddr = sb + OFF_KH + (kbase + v_r) * APB + (dt * 16 + v_c) * 2;
                LDSM_X4_T(vh4, vaddr);
                LDSM_X4_T(vl4, vaddr + APLANE);
                #pragma unroll
                for (int hv = 0; hv < 2; ++hv) {
                    float* d = cacc[dt * 2 + hv];
                    MMA_BF16(d, pAh[kb], vh4[2 * hv], vh4[2 * hv + 1]);
                    MMA_BF16(d, pAh[kb], vl4[2 * hv], vl4[2 * hv + 1]);
                    MMA_BF16(d, pAl[kb], vh4[2 * hv], vh4[2 * hv + 1]);
                }
            }
        }
    }

    // ---- finalize: combine wn halves, divide, mask, write bf16 split ----
    __syncthreads();
    float* CB = (float*)SM;                   // [64][66] f32, aliases Q planes
    if (wn == 1) {
        #pragma unroll
        for (int i = 0; i < 8; ++i) {
            int c = i * 8 + t * 2;
            *(float2*)&CB[r0 * 66 + c] = make_float2(cacc[i][0], cacc[i][1]);
            *(float2*)&CB[r1 * 66 + c] = make_float2(cacc[i][2], cacc[i][3]);
        }
    }
    __syncthreads();
    if (wn == 0) {
        float inv0 = (qmr[r0] != 0.f) ? 1.f / rowL[r0] : 0.f;
        float inv1 = (qmr[r1] != 0.f) ? 1.f / rowL[r1] : 0.f;
        size_t m0r = (size_t)(b * SEQ + q0 + r0) * DIN + h * 64;
        size_t m1r = (size_t)(b * SEQ + q0 + r1) * DIN + h * 64;
        #pragma unroll
        for (int i = 0; i < 8; ++i) {
            int c = i * 8 + t * 2;
            float x0 = (cacc[i][0] + CB[r0 * 66 + c])     * inv0;
            float x1 = (cacc[i][1] + CB[r0 * 66 + c + 1]) * inv0;
            float y0 = (cacc[i][2] + CB[r1 * 66 + c])     * inv1;
            float y1 = (cacc[i][3] + CB[r1 * 66 + c + 1]) * inv1;
            uint32_t hx = pack2(x0, x1);
            uint32_t hy = pack2(y0, y1);
            *(uint32_t*)(g_Xh + m0r + c) = hx;
            *(uint32_t*)(g_Xl + m0r + c) = pack2(x0 - lo_half_f(hx), x1 - hi_half_f(hx));
            *(uint32_t*)(g_Xh + m1r + c) = hy;
            *(uint32_t*)(g_Xl + m1r + c) = pack2(y0 - lo_half_f(hy), y1 - hi_half_f(hy));
        }
    }
}

// =====================================================================
// LayerNorm over last dim (1024), one block per row.
// =====================================================================
__global__ __launch_bounds__(256) void ln_kernel(
    const float* __restrict__ gamma, const float* __restrict__ beta,
    float* __restrict__ out)
{
    __shared__ float red[16];
    __shared__ float s_mu, s_rs;
    const int row = blockIdx.x;
    const int tid = threadIdx.x;
    const float* xr = g_O1 + (size_t)row * DIN;
    float4 x = *(const float4*)(xr + tid * 4);
    float s  = x.x + x.y + x.z + x.w;
    float s2 = x.x * x.x + x.y * x.y + x.z * x.z + x.w * x.w;
    #pragma unroll
    for (int o = 16; o; o >>= 1) {
        s  += __shfl_xor_sync(0xffffffffu, s, o);
        s2 += __shfl_xor_sync(0xffffffffu, s2, o);
    }
    if ((tid & 31) == 0) { red[tid >> 5] = s; red[8 + (tid >> 5)] = s2; }
    __syncthreads();
    if (tid == 0) {
        float ts = 0.f, ts2 = 0.f;
        #pragma unroll
        for (int w = 0; w < 8; w++) { ts += red[w]; ts2 += red[8 + w]; }
        float mu  = ts * (1.f / 1024.f);
        float var = ts2 * (1.f / 1024.f) - mu * mu;
        s_mu = mu; s_rs = rsqrtf(var + 1e-5f);
    }
    __syncthreads();
    float mu = s_mu, rs = s_rs;
    float4 g  = *(const float4*)(gamma + tid * 4);
    float4 be = *(const float4*)(beta  + tid * 4);
    float4 o;
    o.x = (x.x - mu) * rs * g.x + be.x;
    o.y = (x.y - mu) * rs * g.y + be.y;
    o.z = (x.z - mu) * rs * g.z + be.z;
    o.w = (x.w - mu) * rs * g.w + be.w;
    *(float4*)(out + (size_t)row * DIN + tid * 4) = o;
}

// =====================================================================
extern "C" void kernel_launch(void* const* d_in, const int* in_sizes, int n_in,
                              void* d_out, int out_size)
{
    const float* q     = (const float*)d_in[0];
    const float* k     = (const float*)d_in[1];
    const float* v     = (const float*)d_in[2];
    const float* qm    = (const float*)d_in[3];
    const float* km    = (const float*)d_in[4];
    const float* Wq    = (const float*)d_in[5];
    const float* bq    = (const float*)d_in[6];
    const float* Wk    = (const float*)d_in[7];
    const float* bk    = (const float*)d_in[8];
    const float* Wv    = (const float*)d_in[9];
    const float* bv    = (const float*)d_in[10];
    const float* Wf    = (const float*)d_in[11];
    const float* bf    = (const float*)d_in[12];
    const float* gamma = (const float*)d_in[13];
    const float* beta  = (const float*)d_in[14];

    float* out = (float*)d_out;
    float* att = out + OUT1_ELEMS;

    const int cvx_blocks = (int)(OUT1_ELEMS / (4 * 256));   // 4096
    const dim3 cw(32, 32);
    const dim3 gg(DIN / 128, MTOT / 128);                   // (8, 32)

    cvt_x<<<cvx_blocks, 256>>>(q);
    cvt_w<<<cw, 256>>>(Wq);
    gemm_mma<<<gg, 256>>>(bq, nullptr, 0);

    cvt_x<<<cvx_blocks, 256>>>(k);
    cvt_w<<<cw, 256>>>(Wk);
    gemm_mma<<<gg, 256>>>(bk, nullptr, 1);

    cvt_x<<<cvx_blocks, 256>>>(v);
    cvt_w<<<cw, 256>>>(Wv);
    gemm_mma<<<gg, 256>>>(bv, nullptr, 2);

    attn_mma<<<dim3(SEQ / 64, NB * NH), 256>>>(qm, km, att);

    cvt_w<<<cw, 256>>>(Wf);
    gemm_mma<<<gg, 256>>>(bf, v, 3);   // reads g_Xh/g_Xl written by attn finalize

    ln_kernel<<<MTOT, 256>>>(gamma, beta, out);
}